// round 15
// baseline (speedup 1.0000x reference)
#include <cuda_runtime.h>
#include <cuda_fp16.h>
#include <math.h>
#include <stdint.h>

// out = x + Re(IFFT2(ifftshift(fftshift(FFT2(x)) * gain))), x: [4,256,256,256] f32.
//
// Monolithic 3-pass. Warp-FFT (256 = 8 regs x 32 lanes), packed f32x2 (FFMA2),
// fp16 scratch, single-pfma lane butterflies (R14).
// NEW: K2 at 4 CTAs/SM (was 3) with gain loads de-hoisted to their use point
// to fit the 64-reg cap -> +33% warps to hide SHFL latency.

#define NPAIR 512
typedef unsigned long long u64;

__device__ __align__(16) __half2 d_scr1[NPAIR * 256 * 256];   // 128 MiB [p][u][r]
__device__ __align__(16) __half2 d_scr2[NPAIR * 256 * 256];   // 128 MiB [p][r][g_s]
__device__ float  d_ge[256 * 256];    // d_ge[u*256 + sh]: kw=sigW(u), kh=sigH(sh)
__device__ float2 d_w256[256];        // W256^j

// ---------------------------------------------------------------------------
// packed f32x2 primitives
// ---------------------------------------------------------------------------
__device__ __forceinline__ u64 pk(float a, float b) {
    u64 r; asm("mov.b64 %0,{%1,%2};" : "=l"(r) : "f"(a), "f"(b)); return r;
}
__device__ __forceinline__ void upk(u64 p, float& a, float& b) {
    asm("mov.b64 {%0,%1},%2;" : "=f"(a), "=f"(b) : "l"(p));
}
__device__ __forceinline__ u64 bcast(float a) { return pk(a, a); }
__device__ __forceinline__ u64 padd(u64 a, u64 b) {
    u64 r; asm("add.rn.f32x2 %0,%1,%2;" : "=l"(r) : "l"(a), "l"(b)); return r;
}
__device__ __forceinline__ u64 pmul(u64 a, u64 b) {
    u64 r; asm("mul.rn.f32x2 %0,%1,%2;" : "=l"(r) : "l"(a), "l"(b)); return r;
}
__device__ __forceinline__ u64 pfma(u64 a, u64 b, u64 c) {
    u64 r; asm("fma.rn.f32x2 %0,%1,%2,%3;" : "=l"(r) : "l"(a), "l"(b), "l"(c)); return r;
}
#define PNEG1 0xBF800000BF800000ULL
#define PPOS1 0x3F8000003F800000ULL
__device__ __forceinline__ u64 psub(u64 a, u64 b) { return pfma(b, PNEG1, a); }
__device__ __forceinline__ u64 pneg(u64 a) { return a ^ 0x8000000080000000ULL; }
__device__ __forceinline__ u64 shfl64(u64 v, int m) {
    return __shfl_xor_sync(0xffffffffu, v, m);
}

// ---------------------------------------------------------------------------
// packed 8-pt FFT (two independent rows in the f32x2 slots); DIF, natural io.
// ---------------------------------------------------------------------------
template <bool INV>
__device__ __forceinline__ void fft8p(u64 R[8], u64 I[8]) {
    const u64 P_R2 = 0x3F3504F33F3504F3ULL;
#define BF0(i0, i1) { u64 sR = padd(R[i0], R[i1]), sI = padd(I[i0], I[i1]); \
    u64 dR = psub(R[i0], R[i1]), dI = psub(I[i0], I[i1]); \
    R[i0] = sR; I[i0] = sI; R[i1] = dR; I[i1] = dI; }
    BF0(0, 4);
    {   u64 sR = padd(R[1], R[5]), sI = padd(I[1], I[5]);
        u64 dR = psub(R[1], R[5]), dI = psub(I[1], I[5]);
        R[1] = sR; I[1] = sI;
        if (!INV) { R[5] = pmul(padd(dR, dI), P_R2); I[5] = pmul(psub(dI, dR), P_R2); }
        else      { R[5] = pmul(psub(dR, dI), P_R2); I[5] = pmul(padd(dI, dR), P_R2); }
    }
    {   u64 sR = padd(R[2], R[6]), sI = padd(I[2], I[6]);
        u64 dR = psub(R[2], R[6]), dI = psub(I[2], I[6]);
        R[2] = sR; I[2] = sI;
        if (!INV) { R[6] = dI;       I[6] = pneg(dR); }
        else      { R[6] = pneg(dI); I[6] = dR; }
    }
    {   u64 sR = padd(R[3], R[7]), sI = padd(I[3], I[7]);
        u64 dR = psub(R[3], R[7]), dI = psub(I[3], I[7]);
        R[3] = sR; I[3] = sI;
        if (!INV) { R[7] = pmul(psub(dI, dR), P_R2); I[7] = pneg(pmul(padd(dR, dI), P_R2)); }
        else      { R[7] = pneg(pmul(padd(dR, dI), P_R2)); I[7] = pmul(psub(dR, dI), P_R2); }
    }
    BF0(0, 2);
    {   u64 sR = padd(R[1], R[3]), sI = padd(I[1], I[3]);
        u64 dR = psub(R[1], R[3]), dI = psub(I[1], I[3]);
        R[1] = sR; I[1] = sI;
        if (!INV) { R[3] = dI;       I[3] = pneg(dR); }
        else      { R[3] = pneg(dI); I[3] = dR; }
    }
    BF0(4, 6);
    {   u64 sR = padd(R[5], R[7]), sI = padd(I[5], I[7]);
        u64 dR = psub(R[5], R[7]), dI = psub(I[5], I[7]);
        R[5] = sR; I[5] = sI;
        if (!INV) { R[7] = dI;       I[7] = pneg(dR); }
        else      { R[7] = pneg(dI); I[7] = dR; }
    }
    BF0(0, 1); BF0(2, 3); BF0(4, 5); BF0(6, 7);
#undef BF0
    u64 t;
    t = R[1]; R[1] = R[4]; R[4] = t;  t = I[1]; I[1] = I[4]; I[4] = t;
    t = R[3]; R[3] = R[6]; R[6] = t;  t = I[3]; I[3] = I[6]; I[6] = t;
}

__device__ __forceinline__ void twp_fwd(u64 R[8], u64 I[8], const float2* w256s, int t) {
#pragma unroll
    for (int k = 1; k < 8; ++k) {
        float2 w = w256s[k * t];
        u64 wr = bcast(w.x), wi = bcast(w.y);
        u64 nR = psub(pmul(R[k], wr), pmul(I[k], wi));
        I[k] = pfma(R[k], wi, pmul(I[k], wr));
        R[k] = nR;
    }
}
__device__ __forceinline__ void twp_inv(u64 R[8], u64 I[8], const float2* w256s, int t) {
#pragma unroll
    for (int k = 1; k < 8; ++k) {
        float2 w = w256s[k * t];
        u64 wr = bcast(w.x), wi = bcast(w.y);
        u64 nR = pfma(I[k], wi, pmul(R[k], wr));
        I[k] = psub(pmul(I[k], wr), pmul(R[k], wi));
        R[k] = nR;
    }
}

// 32-pt across-lane DIF FFT (fwd): butterfly = r + sgn*o (1 pfma/component),
// then twiddle (identity on down lanes). Natural lanes in, br5 out.
__device__ __forceinline__ void lane32p_fwd(u64 R[8], u64 I[8], const float2* w256s, int t) {
#pragma unroll
    for (int s = 4; s >= 0; --s) {
        const int half = 1 << s;
        const bool up = (t & half) != 0;
        float2 w = w256s[(128 >> s) * (t & (half - 1))];
        const u64 pr = bcast(up ? w.x : 1.0f);
        const u64 pi = bcast(up ? w.y : 0.0f);
        const u64 sgn = up ? PNEG1 : PPOS1;
#pragma unroll
        for (int k = 0; k < 8; ++k) {
            u64 rR = shfl64(R[k], half), rI = shfl64(I[k], half);
            u64 xR = pfma(R[k], sgn, rR);
            u64 xI = pfma(I[k], sgn, rI);
            R[k] = psub(pmul(xR, pr), pmul(xI, pi));
            I[k] = pfma(xR, pi, pmul(xI, pr));
        }
    }
}
// inverse DIT (br5 lanes in, natural out): twiddle-conj then r + sgn*o.
__device__ __forceinline__ void lane32p_inv(u64 R[8], u64 I[8], const float2* w256s, int t) {
#pragma unroll
    for (int s = 0; s <= 4; ++s) {
        const int half = 1 << s;
        const bool up = (t & half) != 0;
        float2 w = w256s[(128 >> s) * (t & (half - 1))];
        const u64 pr = bcast(up ? w.x : 1.0f);
        const u64 pi = bcast(up ? w.y : 0.0f);
        const u64 sgn = up ? PNEG1 : PPOS1;
#pragma unroll
        for (int k = 0; k < 8; ++k) {
            u64 tR = pfma(I[k], pi, pmul(R[k], pr));
            u64 tI = psub(pmul(I[k], pr), pmul(R[k], pi));
            u64 rR = shfl64(tR, half), rI = shfl64(tI, half);
            R[k] = pfma(tR, sgn, rR);
            I[k] = pfma(tI, sgn, rI);
        }
    }
}

// ---------------------------------------------------------------------------
__device__ __forceinline__ float gain_at(int u, int v, const float* w) {
    float y = (float)(u < 128 ? u : u - 256);
    float x = (float)(v < 128 ? v : v - 256);
    float r = sqrtf(y * y + x * x);
    if (!(r > 38.4f)) return 1.0f;                      // 0.3 * 128
    float theta = atan2f(y, x) + 3.14159265358979323846f;
    float t = theta / 0.78539816339744830962f;
    int k = (int)floorf(t);
    return w[k & 7];
}
__device__ __forceinline__ int br5(int z) { return (int)(__brev((unsigned)z) >> 27); }

__global__ void k_init(const float* __restrict__ aw) {
    __shared__ float w[8];
    if (threadIdx.x < 8) w[threadIdx.x] = aw[threadIdx.x];
    __syncthreads();
    const int u  = blockIdx.x;           // W storage: u = 32*k1 + t
    const int sh = threadIdx.x;          // H storage: sh = 8*t + k1
    const int kw = (u >> 5) + 8 * br5(u & 31);
    const int kh = (sh & 7) + 8 * br5(sh >> 3);
    float g1 = gain_at(kh, kw, w);
    float g2 = gain_at((256 - kh) & 255, (256 - kw) & 255, w);
    d_ge[(u << 8) | sh] = 0.5f * (g1 + g2);
    if (u == 0) {
        double ang = -2.0 * 3.14159265358979323846 * (double)sh / 256.0;
        d_w256[sh] = make_float2((float)cos(ang), (float)sin(ang));
    }
}

// ---------------------------------------------------------------------------
// K1: row FFT (2 rows/warp packed); write scr1[p][u][r] via transpose tile.
// ---------------------------------------------------------------------------
#define PT 33
__global__ void __launch_bounds__(256, 4) k_fft_rows(const float* __restrict__ x) {
    __shared__ __half2 tile[256 * PT];
    __shared__ float2 w256s[256];
    const int tid = threadIdx.x;
    w256s[tid] = d_w256[tid];
    __syncthreads();
    const int t = tid & 31;
    const int w = tid >> 5;
    const int p  = blockIdx.x >> 3;
    const int R0 = (blockIdx.x & 7) << 5;

    const float* xa_img = x + ((size_t)p << 17);
    const float* xb_img = xa_img + 65536;

#pragma unroll
    for (int pp = 0; pp < 2; ++pp) {
        const int rl = (w << 2) + (pp << 1);
        const float* xaA = xa_img + ((size_t)(R0 + rl) << 8);
        const float* xaB = xaA + 256;
        const float* xbA = xb_img + ((size_t)(R0 + rl) << 8);
        const float* xbB = xbA + 256;
        u64 R[8], I[8];
#pragma unroll
        for (int j = 0; j < 8; ++j) {
            const int n = (j << 5) + t;
            R[j] = pk(__ldg(xaA + n), __ldg(xaB + n));
            I[j] = pk(__ldg(xbA + n), __ldg(xbB + n));
        }
        fft8p<false>(R, I);
        twp_fwd(R, I, w256s, t);
        lane32p_fwd(R, I, w256s, t);
#pragma unroll
        for (int k1 = 0; k1 < 8; ++k1) {
            float ra, rb, ia, ib;
            upk(R[k1], ra, rb);
            upk(I[k1], ia, ib);
            __half2* dst = &tile[((k1 << 5) + t) * PT + rl];
            dst[0] = __floats2half2_rn(ra, ia);
            dst[1] = __floats2half2_rn(rb, ib);
        }
    }
    __syncthreads();

    const uint32_t* tu = (const uint32_t*)tile;
    const int oct = tid & 7;
#pragma unroll
    for (int it = 0; it < 8; ++it) {
        const int u = (tid >> 3) + (it << 5);
        uint4 q;
        q.x = tu[u * PT + (oct << 2) + 0];
        q.y = tu[u * PT + (oct << 2) + 1];
        q.z = tu[u * PT + (oct << 2) + 2];
        q.w = tu[u * PT + (oct << 2) + 3];
        *(uint4*)(d_scr1 + ((size_t)p << 16) + ((size_t)u << 8) + R0 + (oct << 2)) = q;
    }
}

// ---------------------------------------------------------------------------
// K2: column FFT * gain * IFFT (2 columns/warp packed); scr1 -> scr2.
// 4 CTAs/SM; gain loads at use point (register-pressure relief).
// ---------------------------------------------------------------------------
__global__ void __launch_bounds__(256, 4) k_fft_cols() {
    __shared__ __half2 tile[256 * PT];
    __shared__ float2 w256s[256];
    const int tid = threadIdx.x;
    w256s[tid] = d_w256[tid];
    __syncthreads();
    const int t = tid & 31;
    const int w = tid >> 5;
    const int p = blockIdx.x >> 3;
    const int b = blockIdx.x & 7;

    const __half2* src = d_scr1 + ((size_t)p << 16);

#pragma unroll
    for (int cc = 0; cc < 2; ++cc) {
        const int jA = (w << 2) + (cc << 1);
        const int jB = jA + 1;
        const int uA = ((jA & 7) << 5) + (b << 2) + (jA >> 3);
        const int uB = ((jB & 7) << 5) + (b << 2) + (jB >> 3);

        u64 R[8], I[8];
#pragma unroll
        for (int jr = 0; jr < 8; ++jr) {
            float2 fA = __half22float2(src[((size_t)uA << 8) + (jr << 5) + t]);
            float2 fB = __half22float2(src[((size_t)uB << 8) + (jr << 5) + t]);
            R[jr] = pk(fA.x, fB.x);
            I[jr] = pk(fA.y, fB.y);
        }
        fft8p<false>(R, I);
        twp_fwd(R, I, w256s, t);
        lane32p_fwd(R, I, w256s, t);

        // gain loads at use point (occupancy hides latency now)
        const float4* gA = (const float4*)(d_ge + (uA << 8) + (t << 3));
        const float4* gB = (const float4*)(d_ge + (uB << 8) + (t << 3));
        float4 a0 = __ldg(gA), a1 = __ldg(gA + 1);
        float4 b0 = __ldg(gB), b1 = __ldg(gB + 1);
        const float gav[8] = { a0.x, a0.y, a0.z, a0.w, a1.x, a1.y, a1.z, a1.w };
        const float gbv[8] = { b0.x, b0.y, b0.z, b0.w, b1.x, b1.y, b1.z, b1.w };
#pragma unroll
        for (int k = 0; k < 8; ++k) {
            u64 g = pk(gav[k], gbv[k]);
            R[k] = pmul(R[k], g);
            I[k] = pmul(I[k], g);
        }

        lane32p_inv(R, I, w256s, t);
        twp_inv(R, I, w256s, t);
        fft8p<true>(R, I);

#pragma unroll
        for (int jr = 0; jr < 8; ++jr) {
            float ra, rb, ia, ib;
            upk(R[jr], ra, rb);
            upk(I[jr], ia, ib);
            __half2* dst = &tile[((jr << 5) + t) * PT + jA];
            dst[0] = __floats2half2_rn(ra, ia);
            dst[1] = __floats2half2_rn(rb, ib);
        }
    }
    __syncthreads();

    const uint32_t* tu = (const uint32_t*)tile;
    const int oct = tid & 7;
#pragma unroll
    for (int it = 0; it < 8; ++it) {
        const int row = (tid >> 3) + (it << 5);
        uint4 q;
        q.x = tu[row * PT + (oct << 2) + 0];
        q.y = tu[row * PT + (oct << 2) + 1];
        q.z = tu[row * PT + (oct << 2) + 2];
        q.w = tu[row * PT + (oct << 2) + 3];
        *(uint4*)(d_scr2 + ((size_t)p << 16) + ((size_t)row << 8) + (b << 5) + (oct << 2)) = q;
    }
}

// ---------------------------------------------------------------------------
// K3: inverse warp-FFT along W (2 rows/warp packed) + residual add.
// ---------------------------------------------------------------------------
__global__ void __launch_bounds__(256, 4) k_ifft_rows(const float* __restrict__ x,
                                                      float* __restrict__ out) {
    __shared__ float2 w256s[256];
    const int tid = threadIdx.x;
    w256s[tid] = d_w256[tid];
    __syncthreads();
    const int t = tid & 31;
    const int w = tid >> 5;
    const int gid2 = (blockIdx.x << 3) + w;          // double-row id 0..65535
    const int p  = gid2 >> 7;
    const int rA = (gid2 & 127) << 1;
    const int rB = rA + 1;

    const uint4* sA = (const uint4*)(d_scr2 + ((size_t)p << 16) + ((size_t)rA << 8) + (t << 3));
    const uint4* sB = (const uint4*)(d_scr2 + ((size_t)p << 16) + ((size_t)rB << 8) + (t << 3));
    __half2 hA[8], hB[8];
    ((uint4*)hA)[0] = __ldg(sA);  ((uint4*)hA)[1] = __ldg(sA + 1);
    ((uint4*)hB)[0] = __ldg(sB);  ((uint4*)hB)[1] = __ldg(sB + 1);

    u64 R[8], I[8];
#pragma unroll
    for (int k = 0; k < 8; ++k) {
        float2 fA = __half22float2(hA[k]);
        float2 fB = __half22float2(hB[k]);
        R[k] = pk(fA.x, fB.x);
        I[k] = pk(fA.y, fB.y);
    }

    lane32p_inv(R, I, w256s, t);
    twp_inv(R, I, w256s, t);
    fft8p<true>(R, I);

    const float sc = 1.0f / 65536.0f;
    const size_t base = ((size_t)p << 17);
    const float* xaA = x + base + ((size_t)rA << 8);
    const float* xbA = xaA + 65536;
    const float* xaB = x + base + ((size_t)rB << 8);
    const float* xbB = xaB + 65536;
    float* oaA = out + base + ((size_t)rA << 8);
    float* obA = oaA + 65536;
    float* oaB = out + base + ((size_t)rB << 8);
    float* obB = oaB + 65536;
#pragma unroll
    for (int j = 0; j < 8; ++j) {
        const int n = (j << 5) + t;
        float ra, rb, ia, ib;
        upk(R[j], ra, rb);
        upk(I[j], ia, ib);
        oaA[n] = __ldg(xaA + n) + ra * sc;
        obA[n] = __ldg(xbA + n) + ia * sc;
        oaB[n] = __ldg(xaB + n) + rb * sc;
        obB[n] = __ldg(xbB + n) + ib * sc;
    }
}

// ---------------------------------------------------------------------------
extern "C" void kernel_launch(void* const* d_in, const int* in_sizes, int n_in,
                              void* d_out, int out_size) {
    (void)in_sizes; (void)n_in; (void)out_size;
    const float* x  = (const float*)d_in[0];
    const float* aw = (const float*)d_in[1];
    float* out = (float*)d_out;

    k_init<<<256, 256>>>(aw);
    k_fft_rows<<<4096, 256>>>(x);
    k_fft_cols<<<4096, 256>>>();
    k_ifft_rows<<<8192, 256>>>(x, out);
}

// round 16
// speedup vs baseline: 1.0104x; 1.0104x over previous
#include <cuda_runtime.h>
#include <cuda_fp16.h>
#include <math.h>
#include <stdint.h>

// out = x + Re(IFFT2(ifftshift(fftshift(FFT2(x)) * gain))), x: [4,256,256,256] f32.
//
// Monolithic 3-pass. Warp-FFT (256 = 8 regs x 32 lanes), packed f32x2 (FFMA2),
// fp16 scratch, single-pfma lane butterflies.
// R14 config restored (K2 = (256,3) + hoisted gains). Single change this
// round: K1 at 5 CTAs/SM (mem-heavy pass, reg budget analysis says it fits).

#define NPAIR 512
typedef unsigned long long u64;

__device__ __align__(16) __half2 d_scr1[NPAIR * 256 * 256];   // 128 MiB [p][u][r]
__device__ __align__(16) __half2 d_scr2[NPAIR * 256 * 256];   // 128 MiB [p][r][g_s]
__device__ float  d_ge[256 * 256];    // d_ge[u*256 + sh]: kw=sigW(u), kh=sigH(sh)
__device__ float2 d_w256[256];        // W256^j

// ---------------------------------------------------------------------------
// packed f32x2 primitives
// ---------------------------------------------------------------------------
__device__ __forceinline__ u64 pk(float a, float b) {
    u64 r; asm("mov.b64 %0,{%1,%2};" : "=l"(r) : "f"(a), "f"(b)); return r;
}
__device__ __forceinline__ void upk(u64 p, float& a, float& b) {
    asm("mov.b64 {%0,%1},%2;" : "=f"(a), "=f"(b) : "l"(p));
}
__device__ __forceinline__ u64 bcast(float a) { return pk(a, a); }
__device__ __forceinline__ u64 padd(u64 a, u64 b) {
    u64 r; asm("add.rn.f32x2 %0,%1,%2;" : "=l"(r) : "l"(a), "l"(b)); return r;
}
__device__ __forceinline__ u64 pmul(u64 a, u64 b) {
    u64 r; asm("mul.rn.f32x2 %0,%1,%2;" : "=l"(r) : "l"(a), "l"(b)); return r;
}
__device__ __forceinline__ u64 pfma(u64 a, u64 b, u64 c) {
    u64 r; asm("fma.rn.f32x2 %0,%1,%2,%3;" : "=l"(r) : "l"(a), "l"(b), "l"(c)); return r;
}
#define PNEG1 0xBF800000BF800000ULL
#define PPOS1 0x3F8000003F800000ULL
__device__ __forceinline__ u64 psub(u64 a, u64 b) { return pfma(b, PNEG1, a); }
__device__ __forceinline__ u64 pneg(u64 a) { return a ^ 0x8000000080000000ULL; }
__device__ __forceinline__ u64 shfl64(u64 v, int m) {
    return __shfl_xor_sync(0xffffffffu, v, m);
}

// ---------------------------------------------------------------------------
// packed 8-pt FFT (two independent rows in the f32x2 slots); DIF, natural io.
// ---------------------------------------------------------------------------
template <bool INV>
__device__ __forceinline__ void fft8p(u64 R[8], u64 I[8]) {
    const u64 P_R2 = 0x3F3504F33F3504F3ULL;
#define BF0(i0, i1) { u64 sR = padd(R[i0], R[i1]), sI = padd(I[i0], I[i1]); \
    u64 dR = psub(R[i0], R[i1]), dI = psub(I[i0], I[i1]); \
    R[i0] = sR; I[i0] = sI; R[i1] = dR; I[i1] = dI; }
    BF0(0, 4);
    {   u64 sR = padd(R[1], R[5]), sI = padd(I[1], I[5]);
        u64 dR = psub(R[1], R[5]), dI = psub(I[1], I[5]);
        R[1] = sR; I[1] = sI;
        if (!INV) { R[5] = pmul(padd(dR, dI), P_R2); I[5] = pmul(psub(dI, dR), P_R2); }
        else      { R[5] = pmul(psub(dR, dI), P_R2); I[5] = pmul(padd(dI, dR), P_R2); }
    }
    {   u64 sR = padd(R[2], R[6]), sI = padd(I[2], I[6]);
        u64 dR = psub(R[2], R[6]), dI = psub(I[2], I[6]);
        R[2] = sR; I[2] = sI;
        if (!INV) { R[6] = dI;       I[6] = pneg(dR); }
        else      { R[6] = pneg(dI); I[6] = dR; }
    }
    {   u64 sR = padd(R[3], R[7]), sI = padd(I[3], I[7]);
        u64 dR = psub(R[3], R[7]), dI = psub(I[3], I[7]);
        R[3] = sR; I[3] = sI;
        if (!INV) { R[7] = pmul(psub(dI, dR), P_R2); I[7] = pneg(pmul(padd(dR, dI), P_R2)); }
        else      { R[7] = pneg(pmul(padd(dR, dI), P_R2)); I[7] = pmul(psub(dR, dI), P_R2); }
    }
    BF0(0, 2);
    {   u64 sR = padd(R[1], R[3]), sI = padd(I[1], I[3]);
        u64 dR = psub(R[1], R[3]), dI = psub(I[1], I[3]);
        R[1] = sR; I[1] = sI;
        if (!INV) { R[3] = dI;       I[3] = pneg(dR); }
        else      { R[3] = pneg(dI); I[3] = dR; }
    }
    BF0(4, 6);
    {   u64 sR = padd(R[5], R[7]), sI = padd(I[5], I[7]);
        u64 dR = psub(R[5], R[7]), dI = psub(I[5], I[7]);
        R[5] = sR; I[5] = sI;
        if (!INV) { R[7] = dI;       I[7] = pneg(dR); }
        else      { R[7] = pneg(dI); I[7] = dR; }
    }
    BF0(0, 1); BF0(2, 3); BF0(4, 5); BF0(6, 7);
#undef BF0
    u64 t;
    t = R[1]; R[1] = R[4]; R[4] = t;  t = I[1]; I[1] = I[4]; I[4] = t;
    t = R[3]; R[3] = R[6]; R[6] = t;  t = I[3]; I[3] = I[6]; I[6] = t;
}

__device__ __forceinline__ void twp_fwd(u64 R[8], u64 I[8], const float2* w256s, int t) {
#pragma unroll
    for (int k = 1; k < 8; ++k) {
        float2 w = w256s[k * t];
        u64 wr = bcast(w.x), wi = bcast(w.y);
        u64 nR = psub(pmul(R[k], wr), pmul(I[k], wi));
        I[k] = pfma(R[k], wi, pmul(I[k], wr));
        R[k] = nR;
    }
}
__device__ __forceinline__ void twp_inv(u64 R[8], u64 I[8], const float2* w256s, int t) {
#pragma unroll
    for (int k = 1; k < 8; ++k) {
        float2 w = w256s[k * t];
        u64 wr = bcast(w.x), wi = bcast(w.y);
        u64 nR = pfma(I[k], wi, pmul(R[k], wr));
        I[k] = psub(pmul(I[k], wr), pmul(R[k], wi));
        R[k] = nR;
    }
}

// 32-pt across-lane DIF FFT (fwd): butterfly = r + sgn*o (1 pfma/component),
// then twiddle (identity on down lanes). Natural lanes in, br5 out.
__device__ __forceinline__ void lane32p_fwd(u64 R[8], u64 I[8], const float2* w256s, int t) {
#pragma unroll
    for (int s = 4; s >= 0; --s) {
        const int half = 1 << s;
        const bool up = (t & half) != 0;
        float2 w = w256s[(128 >> s) * (t & (half - 1))];
        const u64 pr = bcast(up ? w.x : 1.0f);
        const u64 pi = bcast(up ? w.y : 0.0f);
        const u64 sgn = up ? PNEG1 : PPOS1;
#pragma unroll
        for (int k = 0; k < 8; ++k) {
            u64 rR = shfl64(R[k], half), rI = shfl64(I[k], half);
            u64 xR = pfma(R[k], sgn, rR);
            u64 xI = pfma(I[k], sgn, rI);
            R[k] = psub(pmul(xR, pr), pmul(xI, pi));
            I[k] = pfma(xR, pi, pmul(xI, pr));
        }
    }
}
// inverse DIT (br5 lanes in, natural out): twiddle-conj then r + sgn*o.
__device__ __forceinline__ void lane32p_inv(u64 R[8], u64 I[8], const float2* w256s, int t) {
#pragma unroll
    for (int s = 0; s <= 4; ++s) {
        const int half = 1 << s;
        const bool up = (t & half) != 0;
        float2 w = w256s[(128 >> s) * (t & (half - 1))];
        const u64 pr = bcast(up ? w.x : 1.0f);
        const u64 pi = bcast(up ? w.y : 0.0f);
        const u64 sgn = up ? PNEG1 : PPOS1;
#pragma unroll
        for (int k = 0; k < 8; ++k) {
            u64 tR = pfma(I[k], pi, pmul(R[k], pr));
            u64 tI = psub(pmul(I[k], pr), pmul(R[k], pi));
            u64 rR = shfl64(tR, half), rI = shfl64(tI, half);
            R[k] = pfma(tR, sgn, rR);
            I[k] = pfma(tI, sgn, rI);
        }
    }
}

// ---------------------------------------------------------------------------
__device__ __forceinline__ float gain_at(int u, int v, const float* w) {
    float y = (float)(u < 128 ? u : u - 256);
    float x = (float)(v < 128 ? v : v - 256);
    float r = sqrtf(y * y + x * x);
    if (!(r > 38.4f)) return 1.0f;                      // 0.3 * 128
    float theta = atan2f(y, x) + 3.14159265358979323846f;
    float t = theta / 0.78539816339744830962f;
    int k = (int)floorf(t);
    return w[k & 7];
}
__device__ __forceinline__ int br5(int z) { return (int)(__brev((unsigned)z) >> 27); }

__global__ void k_init(const float* __restrict__ aw) {
    __shared__ float w[8];
    if (threadIdx.x < 8) w[threadIdx.x] = aw[threadIdx.x];
    __syncthreads();
    const int u  = blockIdx.x;           // W storage: u = 32*k1 + t
    const int sh = threadIdx.x;          // H storage: sh = 8*t + k1
    const int kw = (u >> 5) + 8 * br5(u & 31);
    const int kh = (sh & 7) + 8 * br5(sh >> 3);
    float g1 = gain_at(kh, kw, w);
    float g2 = gain_at((256 - kh) & 255, (256 - kw) & 255, w);
    d_ge[(u << 8) | sh] = 0.5f * (g1 + g2);
    if (u == 0) {
        double ang = -2.0 * 3.14159265358979323846 * (double)sh / 256.0;
        d_w256[sh] = make_float2((float)cos(ang), (float)sin(ang));
    }
}

// ---------------------------------------------------------------------------
// K1: row FFT (2 rows/warp packed); write scr1[p][u][r] via transpose tile.
// 5 CTAs/SM this round (mem-heavy pass; reg budget fits <=51).
// ---------------------------------------------------------------------------
#define PT 33
__global__ void __launch_bounds__(256, 5) k_fft_rows(const float* __restrict__ x) {
    __shared__ __half2 tile[256 * PT];
    __shared__ float2 w256s[256];
    const int tid = threadIdx.x;
    w256s[tid] = d_w256[tid];
    __syncthreads();
    const int t = tid & 31;
    const int w = tid >> 5;
    const int p  = blockIdx.x >> 3;
    const int R0 = (blockIdx.x & 7) << 5;

    const float* xa_img = x + ((size_t)p << 17);
    const float* xb_img = xa_img + 65536;

#pragma unroll
    for (int pp = 0; pp < 2; ++pp) {
        const int rl = (w << 2) + (pp << 1);
        const float* xaA = xa_img + ((size_t)(R0 + rl) << 8);
        const float* xaB = xaA + 256;
        const float* xbA = xb_img + ((size_t)(R0 + rl) << 8);
        const float* xbB = xbA + 256;
        u64 R[8], I[8];
#pragma unroll
        for (int j = 0; j < 8; ++j) {
            const int n = (j << 5) + t;
            R[j] = pk(__ldg(xaA + n), __ldg(xaB + n));
            I[j] = pk(__ldg(xbA + n), __ldg(xbB + n));
        }
        fft8p<false>(R, I);
        twp_fwd(R, I, w256s, t);
        lane32p_fwd(R, I, w256s, t);
#pragma unroll
        for (int k1 = 0; k1 < 8; ++k1) {
            float ra, rb, ia, ib;
            upk(R[k1], ra, rb);
            upk(I[k1], ia, ib);
            __half2* dst = &tile[((k1 << 5) + t) * PT + rl];
            dst[0] = __floats2half2_rn(ra, ia);
            dst[1] = __floats2half2_rn(rb, ib);
        }
    }
    __syncthreads();

    const uint32_t* tu = (const uint32_t*)tile;
    const int oct = tid & 7;
#pragma unroll
    for (int it = 0; it < 8; ++it) {
        const int u = (tid >> 3) + (it << 5);
        uint4 q;
        q.x = tu[u * PT + (oct << 2) + 0];
        q.y = tu[u * PT + (oct << 2) + 1];
        q.z = tu[u * PT + (oct << 2) + 2];
        q.w = tu[u * PT + (oct << 2) + 3];
        *(uint4*)(d_scr1 + ((size_t)p << 16) + ((size_t)u << 8) + R0 + (oct << 2)) = q;
    }
}

// ---------------------------------------------------------------------------
// K2: column FFT * gain * IFFT (2 columns/warp packed); scr1 -> scr2.
// R14 config: 3 CTAs/SM, gain loads hoisted ahead of the forward FFT.
// ---------------------------------------------------------------------------
__global__ void __launch_bounds__(256, 3) k_fft_cols() {
    __shared__ __half2 tile[256 * PT];
    __shared__ float2 w256s[256];
    const int tid = threadIdx.x;
    w256s[tid] = d_w256[tid];
    __syncthreads();
    const int t = tid & 31;
    const int w = tid >> 5;
    const int p = blockIdx.x >> 3;
    const int b = blockIdx.x & 7;

    const __half2* src = d_scr1 + ((size_t)p << 16);

#pragma unroll
    for (int cc = 0; cc < 2; ++cc) {
        const int jA = (w << 2) + (cc << 1);
        const int jB = jA + 1;
        const int uA = ((jA & 7) << 5) + (b << 2) + (jA >> 3);
        const int uB = ((jB & 7) << 5) + (b << 2) + (jB >> 3);

        // hoisted gain loads (in flight during the forward FFT)
        const float4* gA = (const float4*)(d_ge + (uA << 8) + (t << 3));
        const float4* gB = (const float4*)(d_ge + (uB << 8) + (t << 3));
        float4 a0 = __ldg(gA), a1 = __ldg(gA + 1);
        float4 b0 = __ldg(gB), b1 = __ldg(gB + 1);

        u64 R[8], I[8];
#pragma unroll
        for (int jr = 0; jr < 8; ++jr) {
            float2 fA = __half22float2(src[((size_t)uA << 8) + (jr << 5) + t]);
            float2 fB = __half22float2(src[((size_t)uB << 8) + (jr << 5) + t]);
            R[jr] = pk(fA.x, fB.x);
            I[jr] = pk(fA.y, fB.y);
        }
        fft8p<false>(R, I);
        twp_fwd(R, I, w256s, t);
        lane32p_fwd(R, I, w256s, t);

        const float gav[8] = { a0.x, a0.y, a0.z, a0.w, a1.x, a1.y, a1.z, a1.w };
        const float gbv[8] = { b0.x, b0.y, b0.z, b0.w, b1.x, b1.y, b1.z, b1.w };
#pragma unroll
        for (int k = 0; k < 8; ++k) {
            u64 g = pk(gav[k], gbv[k]);
            R[k] = pmul(R[k], g);
            I[k] = pmul(I[k], g);
        }

        lane32p_inv(R, I, w256s, t);
        twp_inv(R, I, w256s, t);
        fft8p<true>(R, I);

#pragma unroll
        for (int jr = 0; jr < 8; ++jr) {
            float ra, rb, ia, ib;
            upk(R[jr], ra, rb);
            upk(I[jr], ia, ib);
            __half2* dst = &tile[((jr << 5) + t) * PT + jA];
            dst[0] = __floats2half2_rn(ra, ia);
            dst[1] = __floats2half2_rn(rb, ib);
        }
    }
    __syncthreads();

    const uint32_t* tu = (const uint32_t*)tile;
    const int oct = tid & 7;
#pragma unroll
    for (int it = 0; it < 8; ++it) {
        const int row = (tid >> 3) + (it << 5);
        uint4 q;
        q.x = tu[row * PT + (oct << 2) + 0];
        q.y = tu[row * PT + (oct << 2) + 1];
        q.z = tu[row * PT + (oct << 2) + 2];
        q.w = tu[row * PT + (oct << 2) + 3];
        *(uint4*)(d_scr2 + ((size_t)p << 16) + ((size_t)row << 8) + (b << 5) + (oct << 2)) = q;
    }
}

// ---------------------------------------------------------------------------
// K3: inverse warp-FFT along W (2 rows/warp packed) + residual add.
// ---------------------------------------------------------------------------
__global__ void __launch_bounds__(256, 4) k_ifft_rows(const float* __restrict__ x,
                                                      float* __restrict__ out) {
    __shared__ float2 w256s[256];
    const int tid = threadIdx.x;
    w256s[tid] = d_w256[tid];
    __syncthreads();
    const int t = tid & 31;
    const int w = tid >> 5;
    const int gid2 = (blockIdx.x << 3) + w;          // double-row id 0..65535
    const int p  = gid2 >> 7;
    const int rA = (gid2 & 127) << 1;
    const int rB = rA + 1;

    const uint4* sA = (const uint4*)(d_scr2 + ((size_t)p << 16) + ((size_t)rA << 8) + (t << 3));
    const uint4* sB = (const uint4*)(d_scr2 + ((size_t)p << 16) + ((size_t)rB << 8) + (t << 3));
    __half2 hA[8], hB[8];
    ((uint4*)hA)[0] = __ldg(sA);  ((uint4*)hA)[1] = __ldg(sA + 1);
    ((uint4*)hB)[0] = __ldg(sB);  ((uint4*)hB)[1] = __ldg(sB + 1);

    u64 R[8], I[8];
#pragma unroll
    for (int k = 0; k < 8; ++k) {
        float2 fA = __half22float2(hA[k]);
        float2 fB = __half22float2(hB[k]);
        R[k] = pk(fA.x, fB.x);
        I[k] = pk(fA.y, fB.y);
    }

    lane32p_inv(R, I, w256s, t);
    twp_inv(R, I, w256s, t);
    fft8p<true>(R, I);

    const float sc = 1.0f / 65536.0f;
    const size_t base = ((size_t)p << 17);
    const float* xaA = x + base + ((size_t)rA << 8);
    const float* xbA = xaA + 65536;
    const float* xaB = x + base + ((size_t)rB << 8);
    const float* xbB = xaB + 65536;
    float* oaA = out + base + ((size_t)rA << 8);
    float* obA = oaA + 65536;
    float* oaB = out + base + ((size_t)rB << 8);
    float* obB = oaB + 65536;
#pragma unroll
    for (int j = 0; j < 8; ++j) {
        const int n = (j << 5) + t;
        float ra, rb, ia, ib;
        upk(R[j], ra, rb);
        upk(I[j], ia, ib);
        oaA[n] = __ldg(xaA + n) + ra * sc;
        obA[n] = __ldg(xbA + n) + ia * sc;
        oaB[n] = __ldg(xaB + n) + rb * sc;
        obB[n] = __ldg(xbB + n) + ib * sc;
    }
}

// ---------------------------------------------------------------------------
extern "C" void kernel_launch(void* const* d_in, const int* in_sizes, int n_in,
                              void* d_out, int out_size) {
    (void)in_sizes; (void)n_in; (void)out_size;
    const float* x  = (const float*)d_in[0];
    const float* aw = (const float*)d_in[1];
    float* out = (float*)d_out;

    k_init<<<256, 256>>>(aw);
    k_fft_rows<<<4096, 256>>>(x);
    k_fft_cols<<<4096, 256>>>();
    k_ifft_rows<<<8192, 256>>>(x, out);
}

// round 17
// speedup vs baseline: 1.0624x; 1.0515x over previous
#include <cuda_runtime.h>
#include <cuda_fp16.h>
#include <math.h>
#include <stdint.h>

// out = x + Re(IFFT2(ifftshift(fftshift(FFT2(x)) * gain))), x: [4,256,256,256] f32.
//
// Monolithic 3-pass. Warp-FFT (256 = 8 regs x 32 lanes), packed f32x2 (FFMA2),
// fp16 scratch, single-pfma lane butterflies. R14 launch configs (proven).
// NEW (K2 only): fwd lane stage s=0 + gain + inv lane stage s=0 merged into
// one butterfly  out = P*self + M*partner,  P = g_e+g_o, M = +/-(g_self-g_gp).

#define NPAIR 512
typedef unsigned long long u64;

__device__ __align__(16) __half2 d_scr1[NPAIR * 256 * 256];   // 128 MiB [p][u][r]
__device__ __align__(16) __half2 d_scr2[NPAIR * 256 * 256];   // 128 MiB [p][r][g_s]
__device__ float  d_ge[256 * 256];    // d_ge[u*256 + sh]: kw=sigW(u), kh=sigH(sh)
__device__ float2 d_w256[256];        // W256^j

// ---------------------------------------------------------------------------
// packed f32x2 primitives
// ---------------------------------------------------------------------------
__device__ __forceinline__ u64 pk(float a, float b) {
    u64 r; asm("mov.b64 %0,{%1,%2};" : "=l"(r) : "f"(a), "f"(b)); return r;
}
__device__ __forceinline__ void upk(u64 p, float& a, float& b) {
    asm("mov.b64 {%0,%1},%2;" : "=f"(a), "=f"(b) : "l"(p));
}
__device__ __forceinline__ u64 bcast(float a) { return pk(a, a); }
__device__ __forceinline__ u64 padd(u64 a, u64 b) {
    u64 r; asm("add.rn.f32x2 %0,%1,%2;" : "=l"(r) : "l"(a), "l"(b)); return r;
}
__device__ __forceinline__ u64 pmul(u64 a, u64 b) {
    u64 r; asm("mul.rn.f32x2 %0,%1,%2;" : "=l"(r) : "l"(a), "l"(b)); return r;
}
__device__ __forceinline__ u64 pfma(u64 a, u64 b, u64 c) {
    u64 r; asm("fma.rn.f32x2 %0,%1,%2,%3;" : "=l"(r) : "l"(a), "l"(b), "l"(c)); return r;
}
#define PNEG1 0xBF800000BF800000ULL
#define PPOS1 0x3F8000003F800000ULL
__device__ __forceinline__ u64 psub(u64 a, u64 b) { return pfma(b, PNEG1, a); }
__device__ __forceinline__ u64 pneg(u64 a) { return a ^ 0x8000000080000000ULL; }
__device__ __forceinline__ u64 shfl64(u64 v, int m) {
    return __shfl_xor_sync(0xffffffffu, v, m);
}

// ---------------------------------------------------------------------------
// packed 8-pt FFT (two independent rows in the f32x2 slots); DIF, natural io.
// ---------------------------------------------------------------------------
template <bool INV>
__device__ __forceinline__ void fft8p(u64 R[8], u64 I[8]) {
    const u64 P_R2 = 0x3F3504F33F3504F3ULL;
#define BF0(i0, i1) { u64 sR = padd(R[i0], R[i1]), sI = padd(I[i0], I[i1]); \
    u64 dR = psub(R[i0], R[i1]), dI = psub(I[i0], I[i1]); \
    R[i0] = sR; I[i0] = sI; R[i1] = dR; I[i1] = dI; }
    BF0(0, 4);
    {   u64 sR = padd(R[1], R[5]), sI = padd(I[1], I[5]);
        u64 dR = psub(R[1], R[5]), dI = psub(I[1], I[5]);
        R[1] = sR; I[1] = sI;
        if (!INV) { R[5] = pmul(padd(dR, dI), P_R2); I[5] = pmul(psub(dI, dR), P_R2); }
        else      { R[5] = pmul(psub(dR, dI), P_R2); I[5] = pmul(padd(dI, dR), P_R2); }
    }
    {   u64 sR = padd(R[2], R[6]), sI = padd(I[2], I[6]);
        u64 dR = psub(R[2], R[6]), dI = psub(I[2], I[6]);
        R[2] = sR; I[2] = sI;
        if (!INV) { R[6] = dI;       I[6] = pneg(dR); }
        else      { R[6] = pneg(dI); I[6] = dR; }
    }
    {   u64 sR = padd(R[3], R[7]), sI = padd(I[3], I[7]);
        u64 dR = psub(R[3], R[7]), dI = psub(I[3], I[7]);
        R[3] = sR; I[3] = sI;
        if (!INV) { R[7] = pmul(psub(dI, dR), P_R2); I[7] = pneg(pmul(padd(dR, dI), P_R2)); }
        else      { R[7] = pneg(pmul(padd(dR, dI), P_R2)); I[7] = pmul(psub(dR, dI), P_R2); }
    }
    BF0(0, 2);
    {   u64 sR = padd(R[1], R[3]), sI = padd(I[1], I[3]);
        u64 dR = psub(R[1], R[3]), dI = psub(I[1], I[3]);
        R[1] = sR; I[1] = sI;
        if (!INV) { R[3] = dI;       I[3] = pneg(dR); }
        else      { R[3] = pneg(dI); I[3] = dR; }
    }
    BF0(4, 6);
    {   u64 sR = padd(R[5], R[7]), sI = padd(I[5], I[7]);
        u64 dR = psub(R[5], R[7]), dI = psub(I[5], I[7]);
        R[5] = sR; I[5] = sI;
        if (!INV) { R[7] = dI;       I[7] = pneg(dR); }
        else      { R[7] = pneg(dI); I[7] = dR; }
    }
    BF0(0, 1); BF0(2, 3); BF0(4, 5); BF0(6, 7);
#undef BF0
    u64 t;
    t = R[1]; R[1] = R[4]; R[4] = t;  t = I[1]; I[1] = I[4]; I[4] = t;
    t = R[3]; R[3] = R[6]; R[6] = t;  t = I[3]; I[3] = I[6]; I[6] = t;
}

__device__ __forceinline__ void twp_fwd(u64 R[8], u64 I[8], const float2* w256s, int t) {
#pragma unroll
    for (int k = 1; k < 8; ++k) {
        float2 w = w256s[k * t];
        u64 wr = bcast(w.x), wi = bcast(w.y);
        u64 nR = psub(pmul(R[k], wr), pmul(I[k], wi));
        I[k] = pfma(R[k], wi, pmul(I[k], wr));
        R[k] = nR;
    }
}
__device__ __forceinline__ void twp_inv(u64 R[8], u64 I[8], const float2* w256s, int t) {
#pragma unroll
    for (int k = 1; k < 8; ++k) {
        float2 w = w256s[k * t];
        u64 wr = bcast(w.x), wi = bcast(w.y);
        u64 nR = pfma(I[k], wi, pmul(R[k], wr));
        I[k] = psub(pmul(I[k], wr), pmul(R[k], wi));
        R[k] = nR;
    }
}

// 32-pt across-lane DIF FFT (fwd): full version, stages s=4..0.
__device__ __forceinline__ void lane32p_fwd(u64 R[8], u64 I[8], const float2* w256s, int t) {
#pragma unroll
    for (int s = 4; s >= 0; --s) {
        const int half = 1 << s;
        const bool up = (t & half) != 0;
        float2 w = w256s[(128 >> s) * (t & (half - 1))];
        const u64 pr = bcast(up ? w.x : 1.0f);
        const u64 pi = bcast(up ? w.y : 0.0f);
        const u64 sgn = up ? PNEG1 : PPOS1;
#pragma unroll
        for (int k = 0; k < 8; ++k) {
            u64 rR = shfl64(R[k], half), rI = shfl64(I[k], half);
            u64 xR = pfma(R[k], sgn, rR);
            u64 xI = pfma(I[k], sgn, rI);
            R[k] = psub(pmul(xR, pr), pmul(xI, pi));
            I[k] = pfma(xR, pi, pmul(xI, pr));
        }
    }
}
// fwd partial: stages s=4..1 only (s=0 merged with gain in K2).
__device__ __forceinline__ void lane32p_fwd_hi(u64 R[8], u64 I[8], const float2* w256s, int t) {
#pragma unroll
    for (int s = 4; s >= 1; --s) {
        const int half = 1 << s;
        const bool up = (t & half) != 0;
        float2 w = w256s[(128 >> s) * (t & (half - 1))];
        const u64 pr = bcast(up ? w.x : 1.0f);
        const u64 pi = bcast(up ? w.y : 0.0f);
        const u64 sgn = up ? PNEG1 : PPOS1;
#pragma unroll
        for (int k = 0; k < 8; ++k) {
            u64 rR = shfl64(R[k], half), rI = shfl64(I[k], half);
            u64 xR = pfma(R[k], sgn, rR);
            u64 xI = pfma(I[k], sgn, rI);
            R[k] = psub(pmul(xR, pr), pmul(xI, pi));
            I[k] = pfma(xR, pi, pmul(xI, pr));
        }
    }
}
// inverse DIT, full version: stages s=0..4 (br5 lanes in, natural out).
__device__ __forceinline__ void lane32p_inv(u64 R[8], u64 I[8], const float2* w256s, int t) {
#pragma unroll
    for (int s = 0; s <= 4; ++s) {
        const int half = 1 << s;
        const bool up = (t & half) != 0;
        float2 w = w256s[(128 >> s) * (t & (half - 1))];
        const u64 pr = bcast(up ? w.x : 1.0f);
        const u64 pi = bcast(up ? w.y : 0.0f);
        const u64 sgn = up ? PNEG1 : PPOS1;
#pragma unroll
        for (int k = 0; k < 8; ++k) {
            u64 tR = pfma(I[k], pi, pmul(R[k], pr));
            u64 tI = psub(pmul(I[k], pr), pmul(R[k], pi));
            u64 rR = shfl64(tR, half), rI = shfl64(tI, half);
            R[k] = pfma(tR, sgn, rR);
            I[k] = pfma(tI, sgn, rI);
        }
    }
}
// inverse partial: stages s=1..4 only (s=0 merged with gain in K2).
__device__ __forceinline__ void lane32p_inv_lo(u64 R[8], u64 I[8], const float2* w256s, int t) {
#pragma unroll
    for (int s = 1; s <= 4; ++s) {
        const int half = 1 << s;
        const bool up = (t & half) != 0;
        float2 w = w256s[(128 >> s) * (t & (half - 1))];
        const u64 pr = bcast(up ? w.x : 1.0f);
        const u64 pi = bcast(up ? w.y : 0.0f);
        const u64 sgn = up ? PNEG1 : PPOS1;
#pragma unroll
        for (int k = 0; k < 8; ++k) {
            u64 tR = pfma(I[k], pi, pmul(R[k], pr));
            u64 tI = psub(pmul(I[k], pr), pmul(R[k], pi));
            u64 rR = shfl64(tR, half), rI = shfl64(tI, half);
            R[k] = pfma(tR, sgn, rR);
            I[k] = pfma(tI, sgn, rI);
        }
    }
}

// ---------------------------------------------------------------------------
__device__ __forceinline__ float gain_at(int u, int v, const float* w) {
    float y = (float)(u < 128 ? u : u - 256);
    float x = (float)(v < 128 ? v : v - 256);
    float r = sqrtf(y * y + x * x);
    if (!(r > 38.4f)) return 1.0f;                      // 0.3 * 128
    float theta = atan2f(y, x) + 3.14159265358979323846f;
    float t = theta / 0.78539816339744830962f;
    int k = (int)floorf(t);
    return w[k & 7];
}
__device__ __forceinline__ int br5(int z) { return (int)(__brev((unsigned)z) >> 27); }

__global__ void k_init(const float* __restrict__ aw) {
    __shared__ float w[8];
    if (threadIdx.x < 8) w[threadIdx.x] = aw[threadIdx.x];
    __syncthreads();
    const int u  = blockIdx.x;           // W storage: u = 32*k1 + t
    const int sh = threadIdx.x;          // H storage: sh = 8*t + k1
    const int kw = (u >> 5) + 8 * br5(u & 31);
    const int kh = (sh & 7) + 8 * br5(sh >> 3);
    float g1 = gain_at(kh, kw, w);
    float g2 = gain_at((256 - kh) & 255, (256 - kw) & 255, w);
    d_ge[(u << 8) | sh] = 0.5f * (g1 + g2);
    if (u == 0) {
        double ang = -2.0 * 3.14159265358979323846 * (double)sh / 256.0;
        d_w256[sh] = make_float2((float)cos(ang), (float)sin(ang));
    }
}

// ---------------------------------------------------------------------------
// K1: row FFT (2 rows/warp packed); write scr1[p][u][r] via transpose tile.
// ---------------------------------------------------------------------------
#define PT 33
__global__ void __launch_bounds__(256, 4) k_fft_rows(const float* __restrict__ x) {
    __shared__ __half2 tile[256 * PT];
    __shared__ float2 w256s[256];
    const int tid = threadIdx.x;
    w256s[tid] = d_w256[tid];
    __syncthreads();
    const int t = tid & 31;
    const int w = tid >> 5;
    const int p  = blockIdx.x >> 3;
    const int R0 = (blockIdx.x & 7) << 5;

    const float* xa_img = x + ((size_t)p << 17);
    const float* xb_img = xa_img + 65536;

#pragma unroll
    for (int pp = 0; pp < 2; ++pp) {
        const int rl = (w << 2) + (pp << 1);
        const float* xaA = xa_img + ((size_t)(R0 + rl) << 8);
        const float* xaB = xaA + 256;
        const float* xbA = xb_img + ((size_t)(R0 + rl) << 8);
        const float* xbB = xbA + 256;
        u64 R[8], I[8];
#pragma unroll
        for (int j = 0; j < 8; ++j) {
            const int n = (j << 5) + t;
            R[j] = pk(__ldg(xaA + n), __ldg(xaB + n));
            I[j] = pk(__ldg(xbA + n), __ldg(xbB + n));
        }
        fft8p<false>(R, I);
        twp_fwd(R, I, w256s, t);
        lane32p_fwd(R, I, w256s, t);
#pragma unroll
        for (int k1 = 0; k1 < 8; ++k1) {
            float ra, rb, ia, ib;
            upk(R[k1], ra, rb);
            upk(I[k1], ia, ib);
            __half2* dst = &tile[((k1 << 5) + t) * PT + rl];
            dst[0] = __floats2half2_rn(ra, ia);
            dst[1] = __floats2half2_rn(rb, ib);
        }
    }
    __syncthreads();

    const uint32_t* tu = (const uint32_t*)tile;
    const int oct = tid & 7;
#pragma unroll
    for (int it = 0; it < 8; ++it) {
        const int u = (tid >> 3) + (it << 5);
        uint4 q;
        q.x = tu[u * PT + (oct << 2) + 0];
        q.y = tu[u * PT + (oct << 2) + 1];
        q.z = tu[u * PT + (oct << 2) + 2];
        q.w = tu[u * PT + (oct << 2) + 3];
        *(uint4*)(d_scr1 + ((size_t)p << 16) + ((size_t)u << 8) + R0 + (oct << 2)) = q;
    }
}

// ---------------------------------------------------------------------------
// K2: column FFT * gain * IFFT (2 columns/warp packed); scr1 -> scr2.
// 3 CTAs/SM, hoisted gains (R14 config). Merged s=0 stages + gain.
// ---------------------------------------------------------------------------
__global__ void __launch_bounds__(256, 3) k_fft_cols() {
    __shared__ __half2 tile[256 * PT];
    __shared__ float2 w256s[256];
    const int tid = threadIdx.x;
    w256s[tid] = d_w256[tid];
    __syncthreads();
    const int t = tid & 31;
    const int w = tid >> 5;
    const int p = blockIdx.x >> 3;
    const int b = blockIdx.x & 7;
    const u64 mneg = (t & 1) ? 0x8000000080000000ULL : 0ULL;   // M sign per lane

    const __half2* src = d_scr1 + ((size_t)p << 16);

#pragma unroll
    for (int cc = 0; cc < 2; ++cc) {
        const int jA = (w << 2) + (cc << 1);
        const int jB = jA + 1;
        const int uA = ((jA & 7) << 5) + (b << 2) + (jA >> 3);
        const int uB = ((jB & 7) << 5) + (b << 2) + (jB >> 3);

        // hoisted gain loads (in flight during the forward FFT)
        const float4* gA = (const float4*)(d_ge + (uA << 8) + (t << 3));
        const float4* gB = (const float4*)(d_ge + (uB << 8) + (t << 3));
        float4 a0 = __ldg(gA), a1 = __ldg(gA + 1);
        float4 b0 = __ldg(gB), b1 = __ldg(gB + 1);

        u64 R[8], I[8];
#pragma unroll
        for (int jr = 0; jr < 8; ++jr) {
            float2 fA = __half22float2(src[((size_t)uA << 8) + (jr << 5) + t]);
            float2 fB = __half22float2(src[((size_t)uB << 8) + (jr << 5) + t]);
            R[jr] = pk(fA.x, fB.x);
            I[jr] = pk(fA.y, fB.y);
        }
        fft8p<false>(R, I);
        twp_fwd(R, I, w256s, t);
        lane32p_fwd_hi(R, I, w256s, t);          // stages s=4..1

        // merged: [fwd s=0] + gain + [inv s=0]  ==  out = P*self + M*partner
        const float gav[8] = { a0.x, a0.y, a0.z, a0.w, a1.x, a1.y, a1.z, a1.w };
        const float gbv[8] = { b0.x, b0.y, b0.z, b0.w, b1.x, b1.y, b1.z, b1.w };
#pragma unroll
        for (int k = 0; k < 8; ++k) {
            u64 g  = pk(gav[k], gbv[k]);
            u64 gp = shfl64(g, 1);               // partner lane's gain
            u64 P  = padd(g, gp);                // g_e + g_o (same both lanes)
            u64 M  = psub(g, gp) ^ mneg;         // g_e - g_o on both lanes
            u64 rR = shfl64(R[k], 1), rI = shfl64(I[k], 1);
            R[k] = pfma(rR, M, pmul(R[k], P));
            I[k] = pfma(rI, M, pmul(I[k], P));
        }

        lane32p_inv_lo(R, I, w256s, t);          // stages s=1..4
        twp_inv(R, I, w256s, t);
        fft8p<true>(R, I);

#pragma unroll
        for (int jr = 0; jr < 8; ++jr) {
            float ra, rb, ia, ib;
            upk(R[jr], ra, rb);
            upk(I[jr], ia, ib);
            __half2* dst = &tile[((jr << 5) + t) * PT + jA];
            dst[0] = __floats2half2_rn(ra, ia);
            dst[1] = __floats2half2_rn(rb, ib);
        }
    }
    __syncthreads();

    const uint32_t* tu = (const uint32_t*)tile;
    const int oct = tid & 7;
#pragma unroll
    for (int it = 0; it < 8; ++it) {
        const int row = (tid >> 3) + (it << 5);
        uint4 q;
        q.x = tu[row * PT + (oct << 2) + 0];
        q.y = tu[row * PT + (oct << 2) + 1];
        q.z = tu[row * PT + (oct << 2) + 2];
        q.w = tu[row * PT + (oct << 2) + 3];
        *(uint4*)(d_scr2 + ((size_t)p << 16) + ((size_t)row << 8) + (b << 5) + (oct << 2)) = q;
    }
}

// ---------------------------------------------------------------------------
// K3: inverse warp-FFT along W (2 rows/warp packed) + residual add.
// ---------------------------------------------------------------------------
__global__ void __launch_bounds__(256, 4) k_ifft_rows(const float* __restrict__ x,
                                                      float* __restrict__ out) {
    __shared__ float2 w256s[256];
    const int tid = threadIdx.x;
    w256s[tid] = d_w256[tid];
    __syncthreads();
    const int t = tid & 31;
    const int w = tid >> 5;
    const int gid2 = (blockIdx.x << 3) + w;          // double-row id 0..65535
    const int p  = gid2 >> 7;
    const int rA = (gid2 & 127) << 1;
    const int rB = rA + 1;

    const uint4* sA = (const uint4*)(d_scr2 + ((size_t)p << 16) + ((size_t)rA << 8) + (t << 3));
    const uint4* sB = (const uint4*)(d_scr2 + ((size_t)p << 16) + ((size_t)rB << 8) + (t << 3));
    __half2 hA[8], hB[8];
    ((uint4*)hA)[0] = __ldg(sA);  ((uint4*)hA)[1] = __ldg(sA + 1);
    ((uint4*)hB)[0] = __ldg(sB);  ((uint4*)hB)[1] = __ldg(sB + 1);

    u64 R[8], I[8];
#pragma unroll
    for (int k = 0; k < 8; ++k) {
        float2 fA = __half22float2(hA[k]);
        float2 fB = __half22float2(hB[k]);
        R[k] = pk(fA.x, fB.x);
        I[k] = pk(fA.y, fB.y);
    }

    lane32p_inv(R, I, w256s, t);
    twp_inv(R, I, w256s, t);
    fft8p<true>(R, I);

    const float sc = 1.0f / 65536.0f;
    const size_t base = ((size_t)p << 17);
    const float* xaA = x + base + ((size_t)rA << 8);
    const float* xbA = xaA + 65536;
    const float* xaB = x + base + ((size_t)rB << 8);
    const float* xbB = xaB + 65536;
    float* oaA = out + base + ((size_t)rA << 8);
    float* obA = oaA + 65536;
    float* oaB = out + base + ((size_t)rB << 8);
    float* obB = oaB + 65536;
#pragma unroll
    for (int j = 0; j < 8; ++j) {
        const int n = (j << 5) + t;
        float ra, rb, ia, ib;
        upk(R[j], ra, rb);
        upk(I[j], ia, ib);
        oaA[n] = __ldg(xaA + n) + ra * sc;
        obA[n] = __ldg(xbA + n) + ia * sc;
        oaB[n] = __ldg(xaB + n) + rb * sc;
        obB[n] = __ldg(xbB + n) + ib * sc;
    }
}

// ---------------------------------------------------------------------------
extern "C" void kernel_launch(void* const* d_in, const int* in_sizes, int n_in,
                              void* d_out, int out_size) {
    (void)in_sizes; (void)n_in; (void)out_size;
    const float* x  = (const float*)d_in[0];
    const float* aw = (const float*)d_in[1];
    float* out = (float*)d_out;

    k_init<<<256, 256>>>(aw);
    k_fft_rows<<<4096, 256>>>(x);
    k_fft_cols<<<4096, 256>>>();
    k_ifft_rows<<<8192, 256>>>(x, out);
}